// round 1
// baseline (speedup 1.0000x reference)
#include <cuda_runtime.h>

// Triplet margin loss:
//   w = exp(W)                                   [384]
//   d_pos[i] = sum_j w[j]*(a[i,j]-p[i,j])^2
//   d_neg[i] = sum_j w[j]*(a[i,j]-n[i,j])^2
//   out = mean( relu(d_pos - d_neg + 1.0) )
//
// HBM-bound streaming reduction: 604 MB read, ~86 us floor at ~7 TB/s.
// Warp-per-row with float4 loads (96 float4 per row = 3 steps of 32 lanes).
// Deterministic: block partials to __device__ scratch, then one reduce kernel.

#define TL_BLOCKS  2048
#define TL_THREADS 256
#define TL_WARPS   (TL_THREADS / 32)

__device__ float g_tl_partials[TL_BLOCKS];

__global__ __launch_bounds__(TL_THREADS, 8)
void triplet_main_kernel(const float* __restrict__ A,
                         const float* __restrict__ P,
                         const float* __restrict__ Ng,
                         const float* __restrict__ W,
                         int N)
{
    __shared__ float4 sw[96];           // exp(W), 384 floats as float4
    __shared__ float  warp_sums[TL_WARPS];

    const int tid  = threadIdx.x;
    const int lane = tid & 31;
    const int warp = tid >> 5;

    // Compute exp(W) once per block into shared.
    if (tid < 96) {
        float4 w = reinterpret_cast<const float4*>(W)[tid];
        w.x = expf(w.x);
        w.y = expf(w.y);
        w.z = expf(w.z);
        w.w = expf(w.w);
        sw[tid] = w;
    }
    __syncthreads();

    const int gwarp  = blockIdx.x * TL_WARPS + warp;
    const int nwarps = gridDim.x * TL_WARPS;

    float acc = 0.0f;   // per-warp (lane 0) loss accumulator

    for (int r = gwarp; r < N; r += nwarps) {
        const float4* a4 = reinterpret_cast<const float4*>(A  + (size_t)r * 384);
        const float4* p4 = reinterpret_cast<const float4*>(P  + (size_t)r * 384);
        const float4* n4 = reinterpret_cast<const float4*>(Ng + (size_t)r * 384);

        float d = 0.0f;  // accumulate (d_pos - d_neg) contribution directly

        #pragma unroll
        for (int k = 0; k < 3; k++) {
            const int j = lane + k * 32;
            const float4 av = a4[j];
            const float4 pv = p4[j];
            const float4 nv = n4[j];
            const float4 wv = sw[j];

            float ex, en;
            ex = av.x - pv.x; en = av.x - nv.x;
            d = fmaf(wv.x, fmaf(ex, ex, -en * en), d);
            ex = av.y - pv.y; en = av.y - nv.y;
            d = fmaf(wv.y, fmaf(ex, ex, -en * en), d);
            ex = av.z - pv.z; en = av.z - nv.z;
            d = fmaf(wv.z, fmaf(ex, ex, -en * en), d);
            ex = av.w - pv.w; en = av.w - nv.w;
            d = fmaf(wv.w, fmaf(ex, ex, -en * en), d);
        }

        // Warp reduction of d = d_pos - d_neg for this row.
        #pragma unroll
        for (int off = 16; off > 0; off >>= 1)
            d += __shfl_xor_sync(0xffffffffu, d, off);

        if (lane == 0)
            acc += fmaxf(d + 1.0f, 0.0f);   // ALPHA = 1.0
    }

    if (lane == 0) warp_sums[warp] = acc;
    __syncthreads();

    if (tid == 0) {
        float s = 0.0f;
        #pragma unroll
        for (int i = 0; i < TL_WARPS; i++) s += warp_sums[i];
        g_tl_partials[blockIdx.x] = s;
    }
}

__global__ void triplet_finalize_kernel(float* __restrict__ out, int N)
{
    __shared__ double sh[256];
    double s = 0.0;
    for (int i = threadIdx.x; i < TL_BLOCKS; i += 256)
        s += (double)g_tl_partials[i];
    sh[threadIdx.x] = s;
    __syncthreads();
    #pragma unroll
    for (int off = 128; off > 0; off >>= 1) {
        if (threadIdx.x < off) sh[threadIdx.x] += sh[threadIdx.x + off];
        __syncthreads();
    }
    if (threadIdx.x == 0)
        out[0] = (float)(sh[0] / (double)N);
}

extern "C" void kernel_launch(void* const* d_in, const int* in_sizes, int n_in,
                              void* d_out, int out_size)
{
    const float* anchor   = (const float*)d_in[0];
    const float* positive = (const float*)d_in[1];
    const float* negative = (const float*)d_in[2];
    const float* W        = (const float*)d_in[3];
    float* out = (float*)d_out;

    const int N = in_sizes[0] / 384;   // 131072 rows

    triplet_main_kernel<<<TL_BLOCKS, TL_THREADS>>>(anchor, positive, negative, W, N);
    triplet_finalize_kernel<<<1, 256>>>(out, N);
}

// round 2
// speedup vs baseline: 1.1786x; 1.1786x over previous
#include <cuda_runtime.h>

// Triplet margin loss, fused single-pass:
//   w = exp(W)                                   [384]
//   d[i] = sum_j w[j]*((a-p)^2 - (a-n)^2)
//   out  = mean( relu(d + 1.0) )
//
// 604 MB streamed from HBM -> memory-bound; ~86 us floor at ~7 TB/s.
// One persistent wave (148 SMs x 4 CTAs), warp-per-row float4 loads,
// block partials + threadfence ticket so the LAST block does the final
// reduction in-kernel (kills the 7.6us standalone finalize kernel).
// Deterministic: final sum reads all partials in fixed order.

#define TL_BLOCKS  592          // 148 SMs * 4 resident CTAs = exactly one wave
#define TL_THREADS 256
#define TL_WARPS   (TL_THREADS / 32)

__device__ float        g_tl_partials[TL_BLOCKS];
__device__ unsigned int g_tl_count = 0;   // self-resetting ticket counter

__global__ __launch_bounds__(TL_THREADS, 4)
void triplet_fused_kernel(const float* __restrict__ A,
                          const float* __restrict__ P,
                          const float* __restrict__ Ng,
                          const float* __restrict__ W,
                          float* __restrict__ out,
                          int N)
{
    __shared__ float4 sw[96];            // exp(W)
    __shared__ float  warp_sums[TL_WARPS];
    __shared__ int    sh_is_last;

    const int tid  = threadIdx.x;
    const int lane = tid & 31;
    const int warp = tid >> 5;

    if (tid < 96) {
        float4 w = reinterpret_cast<const float4*>(W)[tid];
        w.x = expf(w.x);
        w.y = expf(w.y);
        w.z = expf(w.z);
        w.w = expf(w.w);
        sw[tid] = w;
    }
    __syncthreads();

    const int gwarp  = blockIdx.x * TL_WARPS + warp;
    const int nwarps = TL_BLOCKS * TL_WARPS;

    float acc = 0.0f;                    // lane-0 loss accumulator

    for (int r = gwarp; r < N; r += nwarps) {
        const float4* a4 = reinterpret_cast<const float4*>(A  + (size_t)r * 384);
        const float4* p4 = reinterpret_cast<const float4*>(P  + (size_t)r * 384);
        const float4* n4 = reinterpret_cast<const float4*>(Ng + (size_t)r * 384);

        float d = 0.0f;                  // (d_pos - d_neg) partial

        #pragma unroll
        for (int k = 0; k < 3; k++) {
            const int j = lane + k * 32;
            const float4 av = a4[j];
            const float4 pv = p4[j];
            const float4 nv = n4[j];
            const float4 wv = sw[j];

            float ex, en;
            ex = av.x - pv.x; en = av.x - nv.x;
            d = fmaf(wv.x, fmaf(ex, ex, -en * en), d);
            ex = av.y - pv.y; en = av.y - nv.y;
            d = fmaf(wv.y, fmaf(ex, ex, -en * en), d);
            ex = av.z - pv.z; en = av.z - nv.z;
            d = fmaf(wv.z, fmaf(ex, ex, -en * en), d);
            ex = av.w - pv.w; en = av.w - nv.w;
            d = fmaf(wv.w, fmaf(ex, ex, -en * en), d);
        }

        #pragma unroll
        for (int off = 16; off > 0; off >>= 1)
            d += __shfl_xor_sync(0xffffffffu, d, off);

        if (lane == 0)
            acc += fmaxf(d + 1.0f, 0.0f);      // ALPHA = 1.0
    }

    if (lane == 0) warp_sums[warp] = acc;
    __syncthreads();

    // Block partial -> global, then grab a ticket.
    if (tid == 0) {
        float s = 0.0f;
        #pragma unroll
        for (int i = 0; i < TL_WARPS; i++) s += warp_sums[i];
        g_tl_partials[blockIdx.x] = s;
        __threadfence();
        unsigned int v = atomicAdd(&g_tl_count, 1u);
        sh_is_last = (v == TL_BLOCKS - 1);
    }
    __syncthreads();

    // Last block to finish reduces all partials (fixed order -> deterministic).
    if (sh_is_last) {
        __shared__ double fsum[TL_WARPS];

        double s = 0.0;
        for (int i = tid; i < TL_BLOCKS; i += TL_THREADS)
            s += (double)g_tl_partials[i];

        #pragma unroll
        for (int off = 16; off > 0; off >>= 1)
            s += __shfl_xor_sync(0xffffffffu, s, off);
        if (lane == 0) fsum[warp] = s;
        __syncthreads();

        if (tid == 0) {
            double t = 0.0;
            #pragma unroll
            for (int i = 0; i < TL_WARPS; i++) t += fsum[i];
            out[0] = (float)(t / (double)N);
            g_tl_count = 0;              // reset for next graph replay
        }
    }
}

extern "C" void kernel_launch(void* const* d_in, const int* in_sizes, int n_in,
                              void* d_out, int out_size)
{
    const float* anchor   = (const float*)d_in[0];
    const float* positive = (const float*)d_in[1];
    const float* negative = (const float*)d_in[2];
    const float* W        = (const float*)d_in[3];
    float* out = (float*)d_out;

    const int N = in_sizes[0] / 384;     // 131072 rows

    triplet_fused_kernel<<<TL_BLOCKS, TL_THREADS>>>(anchor, positive, negative, W, out, N);
}